// round 3
// baseline (speedup 1.0000x reference)
#include <cuda_runtime.h>
#include <cstdint>
#include <cstddef>

// Problem sizes
#define BATCH 512
#define TSEQ  512
#define DDIM  128
#define HDIM  64

// Scratch: encoder final hidden state [B, H]
__device__ float g_henc[BATCH * HDIM];

// ---------------- helpers ----------------

__device__ __forceinline__ void fma2(unsigned long long &d, unsigned long long a, unsigned long long b) {
    asm("fma.rn.f32x2 %0, %1, %2, %0;" : "+l"(d) : "l"(a), "l"(b));
}

__device__ __forceinline__ float sum2(unsigned long long v) {
    float lo, hi;
    asm("mov.b64 {%0,%1}, %2;" : "=f"(lo), "=f"(hi) : "l"(v));
    return lo + hi;
}

__device__ __forceinline__ float sigf(float x) {
    return __fdividef(1.0f, 1.0f + __expf(-x));
}

__device__ __forceinline__ float tanh_fast(float x) {
    float ax = fabsf(x);
    float e  = __expf(-2.0f * ax);
    float r  = __fdividef(1.0f - e, 1.0f + e);
    return copysignf(r, x);
}

// =============================================================
// Encoder: 128 blocks x 256 threads, 4 batch rows per block.
// Per step: gates[4,256] = x_t[4,128] @ Wih^T + h[4,64] @ Whh^T + b
// Thread = one gate column (C=1), R=4 rows, K in chunks of 4 via f32x2.
// =============================================================

// smem float offsets
#define E_WIH   0                       // 256 * 132
#define E_WHH   (256*132)               // 256 * 68
#define E_XT    (E_WHH + 256*68)        // 2 * 512 (double-buffered x tile)
#define E_H     (E_XT + 1024)           // 256  (h: [4][64])
#define E_GB    (E_H + 256)             // 1024 (gates: [4][256])
#define E_TOT   (E_GB + 1024)

__global__ void __launch_bounds__(256, 1)
lstm_encoder(const float* __restrict__ x,
             const float* __restrict__ Wih,
             const float* __restrict__ Whh,
             const float* __restrict__ bias)
{
    extern __shared__ float sm[];
    const int tid = threadIdx.x;
    const int b0  = blockIdx.x * 4;

    // load weights (padded rows: 132 / 68 floats -> conflict-free LDS.128)
    for (int i = tid; i < 256 * 128; i += 256)
        sm[E_WIH + (i >> 7) * 132 + (i & 127)] = Wih[i];
    for (int i = tid; i < 256 * 64; i += 256)
        sm[E_WHH + (i >> 6) * 68 + (i & 63)] = Whh[i];

    // x tile for t = 0 : [4][128] = 512 floats, 2 per thread
    {
        int j = tid;
        sm[E_XT + j] = x[((size_t)(b0 + (j >> 7)) * TSEQ + 0) * DDIM + (j & 127)];
        j = tid + 256;
        sm[E_XT + j] = x[((size_t)(b0 + (j >> 7)) * TSEQ + 0) * DDIM + (j & 127)];
    }
    sm[E_H + tid] = 0.0f;

    float creg = 0.0f;                 // cell state for (row = tid>>6, dim = tid&63)
    const float breg = bias[tid];      // per-column bias
    const int col = tid;
    __syncthreads();

    for (int t = 0; t < TSEQ; t++) {
        // prefetch next x tile into registers (hidden under the FMAs)
        const int tn = (t + 1 < TSEQ) ? (t + 1) : t;
        int j2 = tid + 256;
        float xa = x[((size_t)(b0 + (tid >> 7)) * TSEQ + tn) * DDIM + (tid & 127)];
        float xb = x[((size_t)(b0 + (j2 >> 7)) * TSEQ + tn) * DDIM + (j2 & 127)];

        // -------- phase A: gate pre-activations --------
        unsigned long long a0 = 0ull, a1 = 0ull, a2 = 0ull, a3 = 0ull;

        const float* xrow = sm + E_XT + (t & 1) * 512;
        const ulonglong2* wi = (const ulonglong2*)(sm + E_WIH + col * 132);
        const ulonglong2* x0 = (const ulonglong2*)(xrow + 0 * 128);
        const ulonglong2* x1 = (const ulonglong2*)(xrow + 1 * 128);
        const ulonglong2* x2 = (const ulonglong2*)(xrow + 2 * 128);
        const ulonglong2* x3 = (const ulonglong2*)(xrow + 3 * 128);
        #pragma unroll
        for (int i = 0; i < 32; i++) {
            ulonglong2 wv = wi[i];
            ulonglong2 v0 = x0[i], v1 = x1[i], v2 = x2[i], v3 = x3[i];
            fma2(a0, wv.x, v0.x); fma2(a0, wv.y, v0.y);
            fma2(a1, wv.x, v1.x); fma2(a1, wv.y, v1.y);
            fma2(a2, wv.x, v2.x); fma2(a2, wv.y, v2.y);
            fma2(a3, wv.x, v3.x); fma2(a3, wv.y, v3.y);
        }
        const ulonglong2* wh = (const ulonglong2*)(sm + E_WHH + col * 68);
        const ulonglong2* h0 = (const ulonglong2*)(sm + E_H + 0);
        const ulonglong2* h1 = (const ulonglong2*)(sm + E_H + 64);
        const ulonglong2* h2 = (const ulonglong2*)(sm + E_H + 128);
        const ulonglong2* h3 = (const ulonglong2*)(sm + E_H + 192);
        #pragma unroll
        for (int i = 0; i < 16; i++) {
            ulonglong2 wv = wh[i];
            ulonglong2 v0 = h0[i], v1 = h1[i], v2 = h2[i], v3 = h3[i];
            fma2(a0, wv.x, v0.x); fma2(a0, wv.y, v0.y);
            fma2(a1, wv.x, v1.x); fma2(a1, wv.y, v1.y);
            fma2(a2, wv.x, v2.x); fma2(a2, wv.y, v2.y);
            fma2(a3, wv.x, v3.x); fma2(a3, wv.y, v3.y);
        }
        sm[E_GB + 0 * 256 + col] = sum2(a0) + breg;
        sm[E_GB + 1 * 256 + col] = sum2(a1) + breg;
        sm[E_GB + 2 * 256 + col] = sum2(a2) + breg;
        sm[E_GB + 3 * 256 + col] = sum2(a3) + breg;
        __syncthreads();

        // -------- phase C: nonlinearity + state update --------
        {
            const int row = tid >> 6;
            const int dim = tid & 63;
            float gi = sm[E_GB + row * 256 + dim];
            float gf = sm[E_GB + row * 256 + 64 + dim];
            float gg = sm[E_GB + row * 256 + 128 + dim];
            float go = sm[E_GB + row * 256 + 192 + dim];
            float iv = sigf(gi), fv = sigf(gf), ov = sigf(go);
            float gv = tanh_fast(gg);
            creg = fv * creg + iv * gv;
            sm[E_H + row * 64 + dim] = ov * tanh_fast(creg);
        }
        // stage prefetched x
        float* xn = sm + E_XT + ((t + 1) & 1) * 512;
        xn[tid] = xa;
        xn[tid + 256] = xb;
        __syncthreads();
    }

    // write final hidden state
    g_henc[(b0 + (tid >> 6)) * HDIM + (tid & 63)] = sm[E_H + tid];
}

// =============================================================
// Decoder: 64 clusters of 2 CTAs (128 blocks), 256 threads, 8 batch
// rows per cluster. CTA rank r owns output dims [r*64, r*64+64):
// its 256 gate columns (4 gates x 64 dims), weights 128KB fp32 in smem.
// Full h[8,128] exchanged per step: own half local, peer half via DSMEM,
// one barrier.cluster per step (release/acquire orders the DSMEM stores).
// xp_d (input projection) is constant over time -> computed once.
// =============================================================

#define D_WHH   0                       // 256 * 132
#define D_XP    (256*132)               // 8 * 256
#define D_HB    (D_XP + 2048)           // 2 * 8 * 128 (double-buffered h)
#define D_GB    (D_HB + 2048)           // 8 * 256
#define D_HS    (D_GB + 2048)           // 8 * 64 (h_enc staging)
#define D_TOT   (D_HS + 512)

__global__ void __launch_bounds__(256, 1) __cluster_dims__(2, 1, 1)
lstm_decoder(const float* __restrict__ Wih,
             const float* __restrict__ Whh,
             const float* __restrict__ bias,
             float* __restrict__ out)
{
    extern __shared__ float sm[];
    const int tid = threadIdx.x;
    unsigned int rank;
    asm("mov.u32 %0, %%cluster_ctarank;" : "=r"(rank));
    const int b0  = (blockIdx.x >> 1) * 8;
    const int col = tid;                                     // local gate col 0..255
    const int Gc  = (col >> 6) * 128 + (int)rank * 64 + (col & 63); // global gate col

    // stage encoder hidden rows [8][64]
    sm[D_HS + tid]       = g_henc[b0 * HDIM + tid];
    sm[D_HS + tid + 256] = g_henc[b0 * HDIM + tid + 256];

    // stage Wih_d rows (for our gate cols) temporarily in the Whh area
    for (int i = tid; i < 256 * 64; i += 256) {
        int c = i >> 6, k = i & 63;
        int gr = (c >> 6) * 128 + (int)rank * 64 + (c & 63);
        sm[D_WHH + c * 68 + k] = Wih[gr * 64 + k];
    }
    __syncthreads();

    // xp_d[8][256] = b + h_enc @ Wih^T   (constant over time)
    {
        float bb = bias[Gc];
        const float* w = sm + D_WHH + col * 68;
        #pragma unroll
        for (int r = 0; r < 8; r++) {
            const float* hv = sm + D_HS + r * 64;
            float acc = bb;
            #pragma unroll
            for (int k = 0; k < 64; k++) acc += w[k] * hv[k];
            sm[D_XP + r * 256 + col] = acc;
        }
    }
    __syncthreads();

    // load recurrent weights Whh_d for our 256 gate cols (padded to 132)
    for (int i = tid; i < 256 * 128; i += 256) {
        int c = i >> 7, k = i & 127;
        int gr = (c >> 6) * 128 + (int)rank * 64 + (c & 63);
        sm[D_WHH + c * 132 + k] = Whh[gr * 128 + k];
    }
    // zero h buffer 0
    for (int i = tid; i < 1024; i += 256) sm[D_HB + i] = 0.0f;
    __syncthreads();

    // peer address of the h-buffer region
    unsigned int hb_local, hb_peer;
    {
        const float* p = sm + D_HB;
        asm("{ .reg .u64 t; cvta.to.shared.u64 t, %1; cvt.u32.u64 %0, t; }"
            : "=r"(hb_local) : "l"(p));
        unsigned int pr = rank ^ 1u;
        asm("mapa.shared::cluster.u32 %0, %1, %2;" : "=r"(hb_peer) : "r"(hb_local), "r"(pr));
    }
    asm volatile("barrier.cluster.arrive.aligned;" ::: "memory");
    asm volatile("barrier.cluster.wait.aligned;"   ::: "memory");

    float c0 = 0.0f, c1 = 0.0f;          // two (row,dim) states per thread
    const int srow = tid >> 5;           // 0..7
    const int sdim = (tid * 2) & 63;     // even dim

    for (int t = 0; t < TSEQ; t++) {
        const float* hcur = sm + D_HB + (t & 1) * 1024;

        // -------- phase A: recurrent gate pre-activations --------
        unsigned long long acc[8];
        #pragma unroll
        for (int r = 0; r < 8; r++) acc[r] = 0ull;
        const ulonglong2* wp = (const ulonglong2*)(sm + D_WHH + col * 132);
        #pragma unroll
        for (int i = 0; i < 32; i++) {
            ulonglong2 wv = wp[i];
            #pragma unroll
            for (int r = 0; r < 8; r++) {
                ulonglong2 hv = ((const ulonglong2*)(hcur + r * 128))[i];
                fma2(acc[r], wv.x, hv.x);
                fma2(acc[r], wv.y, hv.y);
            }
        }
        #pragma unroll
        for (int r = 0; r < 8; r++)
            sm[D_GB + r * 256 + col] = sum2(acc[r]) + sm[D_XP + r * 256 + col];
        __syncthreads();

        // -------- phase C: update 2 states, publish h halves --------
        {
            float2 gi = *(const float2*)(sm + D_GB + srow * 256 + sdim);
            float2 gf = *(const float2*)(sm + D_GB + srow * 256 + 64 + sdim);
            float2 gg = *(const float2*)(sm + D_GB + srow * 256 + 128 + sdim);
            float2 go = *(const float2*)(sm + D_GB + srow * 256 + 192 + sdim);

            float i0 = sigf(gi.x), i1 = sigf(gi.y);
            float f0 = sigf(gf.x), f1 = sigf(gf.y);
            float o0 = sigf(go.x), o1 = sigf(go.y);
            c0 = f0 * c0 + i0 * tanh_fast(gg.x);
            c1 = f1 * c1 + i1 * tanh_fast(gg.y);
            float h0 = o0 * tanh_fast(c0);
            float h1 = o1 * tanh_fast(c1);

            const int off = srow * 128 + (int)rank * 64 + sdim;
            // local half of next h
            *(float2*)(sm + D_HB + ((t + 1) & 1) * 1024 + off) = make_float2(h0, h1);
            // peer half via DSMEM
            unsigned long long pk;
            asm("mov.b64 %0, {%1,%2};" : "=l"(pk) : "f"(h0), "f"(h1));
            unsigned int paddr = hb_peer + (unsigned int)((((t + 1) & 1) * 1024 + off) * 4);
            asm volatile("st.shared::cluster.b64 [%0], %1;" :: "r"(paddr), "l"(pk) : "memory");
            // output
            *(float2*)(out + ((size_t)(b0 + srow) * TSEQ + t) * DDIM + rank * 64 + sdim)
                = make_float2(h0, h1);
        }
        asm volatile("barrier.cluster.arrive.aligned;" ::: "memory");
        asm volatile("barrier.cluster.wait.aligned;"   ::: "memory");
    }
}

// =============================================================
// launch
// =============================================================
extern "C" void kernel_launch(void* const* d_in, const int* in_sizes, int n_in,
                              void* d_out, int out_size)
{
    const float* x     = (const float*)d_in[0];
    const float* Wih_e = (const float*)d_in[1];
    const float* Whh_e = (const float*)d_in[2];
    const float* b_e   = (const float*)d_in[3];
    const float* Wih_d = (const float*)d_in[4];
    const float* Whh_d = (const float*)d_in[5];
    const float* b_d   = (const float*)d_in[6];
    float* out = (float*)d_out;

    const size_t smem_e = (size_t)E_TOT * sizeof(float);   // ~214 KB
    const size_t smem_d = (size_t)D_TOT * sizeof(float);   // ~162 KB
    cudaFuncSetAttribute(lstm_encoder, cudaFuncAttributeMaxDynamicSharedMemorySize, (int)smem_e);
    cudaFuncSetAttribute(lstm_decoder, cudaFuncAttributeMaxDynamicSharedMemorySize, (int)smem_d);

    lstm_encoder<<<128, 256, smem_e>>>(x, Wih_e, Whh_e, b_e);
    lstm_decoder<<<128, 256, smem_d>>>(Wih_d, Whh_d, b_d, out);
}

// round 4
// speedup vs baseline: 1.0051x; 1.0051x over previous
#include <cuda_runtime.h>
#include <cstdint>
#include <cstddef>

// Problem sizes
#define BATCH 512
#define TSEQ  512
#define DDIM  128
#define HDIM  64

// Scratch: encoder final hidden state [B, H]
__device__ float g_henc[BATCH * HDIM];

// ---------------- helpers ----------------

__device__ __forceinline__ void fma2(unsigned long long &d, unsigned long long a, unsigned long long b) {
    asm("fma.rn.f32x2 %0, %1, %2, %0;" : "+l"(d) : "l"(a), "l"(b));
}

__device__ __forceinline__ float sum2(unsigned long long v) {
    float lo, hi;
    asm("mov.b64 {%0,%1}, %2;" : "=f"(lo), "=f"(hi) : "l"(v));
    return lo + hi;
}

__device__ __forceinline__ float sigf(float x) {
    return __fdividef(1.0f, 1.0f + __expf(-x));
}

__device__ __forceinline__ float tanh_fast(float x) {
    float ax = fabsf(x);
    float e  = __expf(-2.0f * ax);
    float r  = __fdividef(1.0f - e, 1.0f + e);
    return copysignf(r, x);
}

// =============================================================
// Encoder: 128 blocks x 256 threads, 4 batch rows per block.
// Per step: gates[4,256] = x_t[4,128] @ Wih^T + h[4,64] @ Whh^T + b
// Thread = one gate column (C=1), R=4 rows, K in chunks of 4 via f32x2.
// =============================================================

// smem float offsets
#define E_WIH   0                       // 256 * 132
#define E_WHH   (256*132)               // 256 * 68
#define E_XT    (E_WHH + 256*68)        // 2 * 512 (double-buffered x tile)
#define E_H     (E_XT + 1024)           // 256  (h: [4][64])
#define E_GB    (E_H + 256)             // 1024 (gates: [4][256])
#define E_TOT   (E_GB + 1024)

__global__ void __launch_bounds__(256, 1)
lstm_encoder(const float* __restrict__ x,
             const float* __restrict__ Wih,
             const float* __restrict__ Whh,
             const float* __restrict__ bias)
{
    extern __shared__ float sm[];
    const int tid = threadIdx.x;
    const int b0  = blockIdx.x * 4;

    // load weights (padded rows: 132 / 68 floats -> conflict-free LDS.128)
    for (int i = tid; i < 256 * 128; i += 256)
        sm[E_WIH + (i >> 7) * 132 + (i & 127)] = Wih[i];
    for (int i = tid; i < 256 * 64; i += 256)
        sm[E_WHH + (i >> 6) * 68 + (i & 63)] = Whh[i];

    // x tile for t = 0 : [4][128] = 512 floats, 2 per thread
    {
        int j = tid;
        sm[E_XT + j] = x[((size_t)(b0 + (j >> 7)) * TSEQ + 0) * DDIM + (j & 127)];
        j = tid + 256;
        sm[E_XT + j] = x[((size_t)(b0 + (j >> 7)) * TSEQ + 0) * DDIM + (j & 127)];
    }
    sm[E_H + tid] = 0.0f;

    float creg = 0.0f;                 // cell state for (row = tid>>6, dim = tid&63)
    const float breg = bias[tid];      // per-column bias
    const int col = tid;
    __syncthreads();

    for (int t = 0; t < TSEQ; t++) {
        // prefetch next x tile into registers (hidden under the FMAs)
        const int tn = (t + 1 < TSEQ) ? (t + 1) : t;
        int j2 = tid + 256;
        float xa = x[((size_t)(b0 + (tid >> 7)) * TSEQ + tn) * DDIM + (tid & 127)];
        float xb = x[((size_t)(b0 + (j2 >> 7)) * TSEQ + tn) * DDIM + (j2 & 127)];

        // -------- phase A: gate pre-activations --------
        unsigned long long a0 = 0ull, a1 = 0ull, a2 = 0ull, a3 = 0ull;

        const float* xrow = sm + E_XT + (t & 1) * 512;
        const ulonglong2* wi = (const ulonglong2*)(sm + E_WIH + col * 132);
        const ulonglong2* x0 = (const ulonglong2*)(xrow + 0 * 128);
        const ulonglong2* x1 = (const ulonglong2*)(xrow + 1 * 128);
        const ulonglong2* x2 = (const ulonglong2*)(xrow + 2 * 128);
        const ulonglong2* x3 = (const ulonglong2*)(xrow + 3 * 128);
        #pragma unroll
        for (int i = 0; i < 32; i++) {
            ulonglong2 wv = wi[i];
            ulonglong2 v0 = x0[i], v1 = x1[i], v2 = x2[i], v3 = x3[i];
            fma2(a0, wv.x, v0.x); fma2(a0, wv.y, v0.y);
            fma2(a1, wv.x, v1.x); fma2(a1, wv.y, v1.y);
            fma2(a2, wv.x, v2.x); fma2(a2, wv.y, v2.y);
            fma2(a3, wv.x, v3.x); fma2(a3, wv.y, v3.y);
        }
        const ulonglong2* wh = (const ulonglong2*)(sm + E_WHH + col * 68);
        const ulonglong2* h0 = (const ulonglong2*)(sm + E_H + 0);
        const ulonglong2* h1 = (const ulonglong2*)(sm + E_H + 64);
        const ulonglong2* h2 = (const ulonglong2*)(sm + E_H + 128);
        const ulonglong2* h3 = (const ulonglong2*)(sm + E_H + 192);
        #pragma unroll
        for (int i = 0; i < 16; i++) {
            ulonglong2 wv = wh[i];
            ulonglong2 v0 = h0[i], v1 = h1[i], v2 = h2[i], v3 = h3[i];
            fma2(a0, wv.x, v0.x); fma2(a0, wv.y, v0.y);
            fma2(a1, wv.x, v1.x); fma2(a1, wv.y, v1.y);
            fma2(a2, wv.x, v2.x); fma2(a2, wv.y, v2.y);
            fma2(a3, wv.x, v3.x); fma2(a3, wv.y, v3.y);
        }
        sm[E_GB + 0 * 256 + col] = sum2(a0) + breg;
        sm[E_GB + 1 * 256 + col] = sum2(a1) + breg;
        sm[E_GB + 2 * 256 + col] = sum2(a2) + breg;
        sm[E_GB + 3 * 256 + col] = sum2(a3) + breg;
        __syncthreads();

        // -------- phase C: nonlinearity + state update --------
        {
            const int row = tid >> 6;
            const int dim = tid & 63;
            float gi = sm[E_GB + row * 256 + dim];
            float gf = sm[E_GB + row * 256 + 64 + dim];
            float gg = sm[E_GB + row * 256 + 128 + dim];
            float go = sm[E_GB + row * 256 + 192 + dim];
            float iv = sigf(gi), fv = sigf(gf), ov = sigf(go);
            float gv = tanh_fast(gg);
            creg = fv * creg + iv * gv;
            sm[E_H + row * 64 + dim] = ov * tanh_fast(creg);
        }
        // stage prefetched x
        float* xn = sm + E_XT + ((t + 1) & 1) * 512;
        xn[tid] = xa;
        xn[tid + 256] = xb;
        __syncthreads();
    }

    // write final hidden state
    g_henc[(b0 + (tid >> 6)) * HDIM + (tid & 63)] = sm[E_H + tid];
}

// =============================================================
// Decoder: 64 clusters of 2 CTAs (128 blocks), 256 threads, 8 batch
// rows per cluster. CTA rank r owns output dims [r*64, r*64+64):
// its 256 gate columns (4 gates x 64 dims), weights 128KB fp32 in smem.
// Full h[8,128] exchanged per step: own half local, peer half via DSMEM,
// one barrier.cluster per step (release/acquire orders the DSMEM stores).
// xp_d (input projection) is constant over time -> computed once.
// =============================================================

#define D_WHH   0                       // 256 * 132
#define D_XP    (256*132)               // 8 * 256
#define D_HB    (D_XP + 2048)           // 2 * 8 * 128 (double-buffered h)
#define D_GB    (D_HB + 2048)           // 8 * 256
#define D_HS    (D_GB + 2048)           // 8 * 64 (h_enc staging)
#define D_TOT   (D_HS + 512)

__global__ void __launch_bounds__(256, 1) __cluster_dims__(2, 1, 1)
lstm_decoder(const float* __restrict__ Wih,
             const float* __restrict__ Whh,
             const float* __restrict__ bias,
             float* __restrict__ out)
{
    extern __shared__ float sm[];
    const int tid = threadIdx.x;
    unsigned int rank;
    asm("mov.u32 %0, %%cluster_ctarank;" : "=r"(rank));
    const int b0  = (blockIdx.x >> 1) * 8;
    const int col = tid;                                     // local gate col 0..255
    const int Gc  = (col >> 6) * 128 + (int)rank * 64 + (col & 63); // global gate col

    // stage encoder hidden rows [8][64]
    sm[D_HS + tid]       = g_henc[b0 * HDIM + tid];
    sm[D_HS + tid + 256] = g_henc[b0 * HDIM + tid + 256];

    // stage Wih_d rows (for our gate cols) temporarily in the Whh area
    for (int i = tid; i < 256 * 64; i += 256) {
        int c = i >> 6, k = i & 63;
        int gr = (c >> 6) * 128 + (int)rank * 64 + (c & 63);
        sm[D_WHH + c * 68 + k] = Wih[gr * 64 + k];
    }
    __syncthreads();

    // xp_d[8][256] = b + h_enc @ Wih^T   (constant over time)
    {
        float bb = bias[Gc];
        const float* w = sm + D_WHH + col * 68;
        #pragma unroll
        for (int r = 0; r < 8; r++) {
            const float* hv = sm + D_HS + r * 64;
            float acc = bb;
            #pragma unroll
            for (int k = 0; k < 64; k++) acc += w[k] * hv[k];
            sm[D_XP + r * 256 + col] = acc;
        }
    }
    __syncthreads();

    // load recurrent weights Whh_d for our 256 gate cols (padded to 132)
    for (int i = tid; i < 256 * 128; i += 256) {
        int c = i >> 7, k = i & 127;
        int gr = (c >> 6) * 128 + (int)rank * 64 + (c & 63);
        sm[D_WHH + c * 132 + k] = Whh[gr * 128 + k];
    }
    // zero h buffer 0
    for (int i = tid; i < 1024; i += 256) sm[D_HB + i] = 0.0f;
    __syncthreads();

    // peer address of the h-buffer region
    unsigned int hb_local, hb_peer;
    {
        const float* p = sm + D_HB;
        asm("{ .reg .u64 t; cvta.to.shared.u64 t, %1; cvt.u32.u64 %0, t; }"
            : "=r"(hb_local) : "l"(p));
        unsigned int pr = rank ^ 1u;
        asm("mapa.shared::cluster.u32 %0, %1, %2;" : "=r"(hb_peer) : "r"(hb_local), "r"(pr));
    }
    asm volatile("barrier.cluster.arrive.aligned;" ::: "memory");
    asm volatile("barrier.cluster.wait.aligned;"   ::: "memory");

    float c0 = 0.0f, c1 = 0.0f;          // two (row,dim) states per thread
    const int srow = tid >> 5;           // 0..7
    const int sdim = (tid * 2) & 63;     // even dim

    for (int t = 0; t < TSEQ; t++) {
        const float* hcur = sm + D_HB + (t & 1) * 1024;

        // -------- phase A: recurrent gate pre-activations --------
        unsigned long long acc[8];
        #pragma unroll
        for (int r = 0; r < 8; r++) acc[r] = 0ull;
        const ulonglong2* wp = (const ulonglong2*)(sm + D_WHH + col * 132);
        #pragma unroll
        for (int i = 0; i < 32; i++) {
            ulonglong2 wv = wp[i];
            #pragma unroll
            for (int r = 0; r < 8; r++) {
                ulonglong2 hv = ((const ulonglong2*)(hcur + r * 128))[i];
                fma2(acc[r], wv.x, hv.x);
                fma2(acc[r], wv.y, hv.y);
            }
        }
        #pragma unroll
        for (int r = 0; r < 8; r++)
            sm[D_GB + r * 256 + col] = sum2(acc[r]) + sm[D_XP + r * 256 + col];
        __syncthreads();

        // -------- phase C: update 2 states, publish h halves --------
        {
            float2 gi = *(const float2*)(sm + D_GB + srow * 256 + sdim);
            float2 gf = *(const float2*)(sm + D_GB + srow * 256 + 64 + sdim);
            float2 gg = *(const float2*)(sm + D_GB + srow * 256 + 128 + sdim);
            float2 go = *(const float2*)(sm + D_GB + srow * 256 + 192 + sdim);

            float i0 = sigf(gi.x), i1 = sigf(gi.y);
            float f0 = sigf(gf.x), f1 = sigf(gf.y);
            float o0 = sigf(go.x), o1 = sigf(go.y);
            c0 = f0 * c0 + i0 * tanh_fast(gg.x);
            c1 = f1 * c1 + i1 * tanh_fast(gg.y);
            float h0 = o0 * tanh_fast(c0);
            float h1 = o1 * tanh_fast(c1);

            const int off = srow * 128 + (int)rank * 64 + sdim;
            // local half of next h
            *(float2*)(sm + D_HB + ((t + 1) & 1) * 1024 + off) = make_float2(h0, h1);
            // peer half via DSMEM
            unsigned long long pk;
            asm("mov.b64 %0, {%1,%2};" : "=l"(pk) : "f"(h0), "f"(h1));
            unsigned int paddr = hb_peer + (unsigned int)((((t + 1) & 1) * 1024 + off) * 4);
            asm volatile("st.shared::cluster.b64 [%0], %1;" :: "r"(paddr), "l"(pk) : "memory");
            // output
            *(float2*)(out + ((size_t)(b0 + srow) * TSEQ + t) * DDIM + rank * 64 + sdim)
                = make_float2(h0, h1);
        }
        asm volatile("barrier.cluster.arrive.aligned;" ::: "memory");
        asm volatile("barrier.cluster.wait.aligned;"   ::: "memory");
    }
}

// =============================================================
// launch
// =============================================================
extern "C" void kernel_launch(void* const* d_in, const int* in_sizes, int n_in,
                              void* d_out, int out_size)
{
    const float* x     = (const float*)d_in[0];
    const float* Wih_e = (const float*)d_in[1];
    const float* Whh_e = (const float*)d_in[2];
    const float* b_e   = (const float*)d_in[3];
    const float* Wih_d = (const float*)d_in[4];
    const float* Whh_d = (const float*)d_in[5];
    const float* b_d   = (const float*)d_in[6];
    float* out = (float*)d_out;

    const size_t smem_e = (size_t)E_TOT * sizeof(float);   // ~214 KB
    const size_t smem_d = (size_t)D_TOT * sizeof(float);   // ~162 KB
    cudaFuncSetAttribute(lstm_encoder, cudaFuncAttributeMaxDynamicSharedMemorySize, (int)smem_e);
    cudaFuncSetAttribute(lstm_decoder, cudaFuncAttributeMaxDynamicSharedMemorySize, (int)smem_d);

    lstm_encoder<<<128, 256, smem_e>>>(x, Wih_e, Whh_e, b_e);
    lstm_decoder<<<128, 256, smem_d>>>(Wih_d, Whh_d, b_d, out);
}

// round 5
// speedup vs baseline: 1.2437x; 1.2374x over previous
#include <cuda_runtime.h>
#include <cstdint>
#include <cstddef>

#define BATCH 512
#define TSEQ  512
#define DDIM  128
#define HDIM  64

// Scratch: encoder final hidden [B,H]; encoder input projections [B*T, 256]
__device__ float g_henc[BATCH * HDIM];
__device__ float g_xp[(size_t)BATCH * TSEQ * 256];

// ---------------- helpers ----------------

__device__ __forceinline__ void fma2(unsigned long long &d, unsigned long long a, unsigned long long b) {
    asm("fma.rn.f32x2 %0, %1, %2, %0;" : "+l"(d) : "l"(a), "l"(b));
}
__device__ __forceinline__ unsigned long long pack2(float lo, float hi) {
    unsigned long long r;
    asm("mov.b64 %0, {%1,%2};" : "=l"(r) : "f"(lo), "f"(hi));
    return r;
}
__device__ __forceinline__ float sum2(unsigned long long v) {
    float lo, hi;
    asm("mov.b64 {%0,%1}, %2;" : "=f"(lo), "=f"(hi) : "l"(v));
    return lo + hi;
}
__device__ __forceinline__ float sigf(float x) {
    return __fdividef(1.0f, 1.0f + __expf(-x));
}
__device__ __forceinline__ float tanh_fast(float x) {
    float ax = fabsf(x);
    float e  = __expf(-2.0f * ax);
    float r  = __fdividef(1.0f - e, 1.0f + e);
    return copysignf(r, x);
}
__device__ __forceinline__ unsigned smaddr(const void* p) {
    unsigned r;
    asm("{ .reg .u64 t; cvta.to.shared.u64 t, %1; cvt.u32.u64 %0, t; }" : "=r"(r) : "l"(p));
    return r;
}
#define CLUSTER_BAR() do { \
    asm volatile("barrier.cluster.arrive.aligned;" ::: "memory"); \
    asm volatile("barrier.cluster.wait.aligned;"   ::: "memory"); } while (0)

// =============================================================
// Kernel 1: encoder input projections (time-parallel GEMM)
// g_xp[(b*T+t)*256 + c] = b_e[c] + sum_k x[b,t,k] * Wih_e[c,k]
// Grid 2048 x 512: CTA = (b = bx>>2, quarter q = bx&3), 16 row-tiles of 8.
// Thread: cg=tid>>2 (cols cg, cg+128), ks=tid&3 (k-interleave mod 4).
// Weights live in registers; x tile broadcast from smem; shuffle-reduce.
// =============================================================
__global__ void __launch_bounds__(512, 1)
xp_gemm(const float* __restrict__ x,
        const float* __restrict__ Wih,
        const float* __restrict__ bias)
{
    __shared__ float xs[2][8 * 128];
    const int tid = threadIdx.x;
    const int cg = tid >> 2, ks = tid & 3;
    const int c0 = cg, c1 = cg + 128;
    const int b  = blockIdx.x >> 2;
    const int q  = blockIdx.x & 3;

    unsigned long long wa[16], wb[16];
#pragma unroll
    for (int j = 0; j < 8; j++) {
        float4 f = *(const float4*)(Wih + c0 * 128 + 16 * j + 4 * ks);
        wa[2*j] = pack2(f.x, f.y); wa[2*j+1] = pack2(f.z, f.w);
        f = *(const float4*)(Wih + c1 * 128 + 16 * j + 4 * ks);
        wb[2*j] = pack2(f.x, f.y); wb[2*j+1] = pack2(f.z, f.w);
    }
    const float bc0 = bias[c0], bc1 = bias[c1];
    const int r0 = 2 * ks, r1 = r0 + 1;

    const float* xbase = x + ((size_t)b * TSEQ + (size_t)q * 128) * DDIM;
    *(float2*)(&xs[0][tid * 2]) = *(const float2*)(xbase + tid * 2);
    __syncthreads();

    for (int tile = 0; tile < 16; tile++) {
        const int cur = tile & 1, nxt = cur ^ 1;
        float2 pf = make_float2(0.f, 0.f);
        if (tile + 1 < 16)
            pf = *(const float2*)(xbase + (size_t)(tile + 1) * 1024 + tid * 2);

        unsigned long long A0[8], A1[8];
#pragma unroll
        for (int r = 0; r < 8; r++) { A0[r] = 0ull; A1[r] = 0ull; }
#pragma unroll
        for (int j = 0; j < 8; j++) {
#pragma unroll
            for (int r = 0; r < 8; r++) {
                ulonglong2 hv = *(const ulonglong2*)(&xs[cur][r * 128 + 16 * j + 4 * ks]);
                fma2(A0[r], wa[2*j], hv.x); fma2(A0[r], wa[2*j+1], hv.y);
                fma2(A1[r], wb[2*j], hv.x); fma2(A1[r], wb[2*j+1], hv.y);
            }
        }
        float s0[8], s1[8];
#pragma unroll
        for (int r = 0; r < 8; r++) {
            float u = sum2(A0[r]); u += __shfl_xor_sync(~0u, u, 1); u += __shfl_xor_sync(~0u, u, 2); s0[r] = u;
            float v = sum2(A1[r]); v += __shfl_xor_sync(~0u, v, 1); v += __shfl_xor_sync(~0u, v, 2); s1[r] = v;
        }
        float v00 = 0.f, v01 = 0.f, v10 = 0.f, v11 = 0.f;
#pragma unroll
        for (int r = 0; r < 8; r++) {
            if (r == r0) { v00 = s0[r]; v01 = s1[r]; }
            if (r == r1) { v10 = s0[r]; v11 = s1[r]; }
        }
        const size_t row0 = (size_t)b * TSEQ + (size_t)q * 128 + (size_t)tile * 8;
        g_xp[(row0 + r0) * 256 + c0] = v00 + bc0;
        g_xp[(row0 + r0) * 256 + c1] = v01 + bc1;
        g_xp[(row0 + r1) * 256 + c0] = v10 + bc0;
        g_xp[(row0 + r1) * 256 + c1] = v11 + bc1;

        if (tile + 1 < 16) *(float2*)(&xs[nxt][tid * 2]) = pf;
        __syncthreads();
    }
}

// =============================================================
// Kernel 2: encoder recurrence. 128 CTAs x 512 thr, 4 batch rows/CTA.
// Only h @ Whh^T (K=64) per step; xp streamed from g_xp with prefetch.
// Thread: cg=tid>>1 (1 col), ks=tid&1 (k mod 2). Whh slice in registers.
// =============================================================
__global__ void __launch_bounds__(512, 1)
lstm_encoder(const float* __restrict__ Whh)
{
    __shared__ float HB[2 * 4 * 64];      // h double buffer
    __shared__ float XPs[2 * 4 * 256];    // xp double buffer
    __shared__ float G[4 * 260];          // gate pre-activations (padded)
    const int tid = threadIdx.x;
    const int b0  = blockIdx.x * 4;
    const int cg  = tid >> 1, ks = tid & 1;

    unsigned long long w[16];
#pragma unroll
    for (int j = 0; j < 8; j++) {
        float4 f = *(const float4*)(Whh + cg * 64 + 8 * j + 4 * ks);
        w[2*j] = pack2(f.x, f.y); w[2*j+1] = pack2(f.z, f.w);
    }

    const int pr = tid >> 7;              // xp staging row 0..3
    const int pc = (tid & 127) * 2;       // xp staging col pair
    const float* xpsrc = g_xp + (size_t)(b0 + pr) * TSEQ * 256 + pc;

    if (tid < 256) HB[tid] = 0.0f;
    *(float2*)(&XPs[pr * 256 + pc]) = *(const float2*)(xpsrc);   // t = 0
    __syncthreads();

    float creg = 0.0f;
    const int sr = tid >> 6, sd = tid & 63;   // state mapping (tid < 256)

    for (int t = 0; t < TSEQ; t++) {
        const int cur = t & 1, nxt = cur ^ 1;
        const int tn = (t + 1 < TSEQ) ? t + 1 : t;
        float2 pf = *(const float2*)(xpsrc + (size_t)tn * 256);

        const float* hc = HB + cur * 256;
        unsigned long long a0 = 0ull, a1 = 0ull, a2 = 0ull, a3 = 0ull;
#pragma unroll
        for (int j = 0; j < 8; j++) {
            ulonglong2 h0 = *(const ulonglong2*)(hc + 0 * 64 + 8 * j + 4 * ks);
            ulonglong2 h1 = *(const ulonglong2*)(hc + 1 * 64 + 8 * j + 4 * ks);
            ulonglong2 h2 = *(const ulonglong2*)(hc + 2 * 64 + 8 * j + 4 * ks);
            ulonglong2 h3 = *(const ulonglong2*)(hc + 3 * 64 + 8 * j + 4 * ks);
            fma2(a0, w[2*j], h0.x); fma2(a0, w[2*j+1], h0.y);
            fma2(a1, w[2*j], h1.x); fma2(a1, w[2*j+1], h1.y);
            fma2(a2, w[2*j], h2.x); fma2(a2, w[2*j+1], h2.y);
            fma2(a3, w[2*j], h3.x); fma2(a3, w[2*j+1], h3.y);
        }
        float s0 = sum2(a0); s0 += __shfl_xor_sync(~0u, s0, 1);
        float s1 = sum2(a1); s1 += __shfl_xor_sync(~0u, s1, 1);
        float s2 = sum2(a2); s2 += __shfl_xor_sync(~0u, s2, 1);
        float s3 = sum2(a3); s3 += __shfl_xor_sync(~0u, s3, 1);
        if (ks == 0) { G[0 * 260 + cg] = s0; G[1 * 260 + cg] = s1; }
        else         { G[2 * 260 + cg] = s2; G[3 * 260 + cg] = s3; }
        __syncthreads();

        if (tid < 256) {
            const float* xp = XPs + cur * 1024 + sr * 256;
            float gi = G[sr * 260 +       sd] + xp[      sd];
            float gf = G[sr * 260 +  64 + sd] + xp[ 64 + sd];
            float gg = G[sr * 260 + 128 + sd] + xp[128 + sd];
            float go = G[sr * 260 + 192 + sd] + xp[192 + sd];
            float iv = sigf(gi), fv = sigf(gf), ov = sigf(go);
            creg = fv * creg + iv * tanh_fast(gg);
            float hv = ov * tanh_fast(creg);
            HB[nxt * 256 + sr * 64 + sd] = hv;
            if (t == TSEQ - 1) g_henc[(b0 + sr) * HDIM + sd] = hv;
        }
        *(float2*)(&XPs[nxt * 1024 + pr * 256 + pc]) = pf;
        __syncthreads();
    }
}

// =============================================================
// Kernel 3: decoder. 64 clusters x 2 CTAs, 512 thr, 8 batch rows/cluster.
// CTA rank owns 64 of 128 output dims (256 gate cols). Whh slice in
// registers (64 regs/thread). h exchanged via DSMEM + cluster barrier.
// xp constant over time -> registers. Shuffle k-reduction (4 lanes).
// =============================================================
__global__ void __launch_bounds__(512, 1) __cluster_dims__(2, 1, 1)
lstm_decoder(const float* __restrict__ Wih,
             const float* __restrict__ Whh,
             const float* __restrict__ bias,
             float* __restrict__ out)
{
    __shared__ float HB[2 * 8 * 128];   // h double buffer (full 128 dims)
    __shared__ float G[8 * 260];        // gates (padded)
    __shared__ float XP[8 * 256];       // input-projection staging
    __shared__ float HS[8 * 64];        // h_enc staging
    const int tid = threadIdx.x;
    unsigned rank; asm("mov.u32 %0, %%cluster_ctarank;" : "=r"(rank));
    const int b0 = (blockIdx.x >> 1) * 8;
    const int cg = tid >> 2, ks = tid & 3;
    const int c0 = cg, c1 = cg + 128;
    const int g0 = (c0 >> 6) * 128 + (int)rank * 64 + (c0 & 63);
    const int g1 = (c1 >> 6) * 128 + (int)rank * 64 + (c1 & 63);

    unsigned long long wa[16], wb[16];
#pragma unroll
    for (int j = 0; j < 8; j++) {
        float4 f = *(const float4*)(Whh + g0 * 128 + 16 * j + 4 * ks);
        wa[2*j] = pack2(f.x, f.y); wa[2*j+1] = pack2(f.z, f.w);
        f = *(const float4*)(Whh + g1 * 128 + 16 * j + 4 * ks);
        wb[2*j] = pack2(f.x, f.y); wb[2*j+1] = pack2(f.z, f.w);
    }

    HS[tid] = g_henc[b0 * HDIM + tid];
    HB[tid] = 0.0f; HB[tid + 512] = 0.0f;   // zero buffer 0
    __syncthreads();

    // xp[r][c] = b + h_enc[r] . Wih[gr(c)]   (constant over time)
#pragma unroll
    for (int m = 0; m < 4; m++) {
        int idx = m * 512 + tid;
        int r = idx >> 8, c = idx & 255;
        int gr = (c >> 6) * 128 + (int)rank * 64 + (c & 63);
        const float* wv = Wih + gr * 64;
        const float* hv = HS + r * 64;
        float acc = bias[gr];
#pragma unroll
        for (int k = 0; k < 64; k++) acc += wv[k] * hv[k];
        XP[r * 256 + c] = acc;
    }
    __syncthreads();

    const int r0 = 2 * ks, r1 = r0 + 1;
    const float xp00 = XP[r0 * 256 + c0], xp01 = XP[r0 * 256 + c1];
    const float xp10 = XP[r1 * 256 + c0], xp11 = XP[r1 * 256 + c1];

    unsigned hb_peer;
    {
        unsigned loc = smaddr(HB);
        asm("mapa.shared::cluster.u32 %0, %1, %2;" : "=r"(hb_peer) : "r"(loc), "r"(rank ^ 1u));
    }
    CLUSTER_BAR();

    float creg = 0.0f;
    const int sr = tid >> 6, sd = tid & 63;
    float* outp = out + (size_t)(b0 + sr) * TSEQ * DDIM + rank * 64 + sd;
    const int hoff = sr * 128 + (int)rank * 64 + sd;

    for (int t = 0; t < TSEQ; t++) {
        const int cur = t & 1, nxt = cur ^ 1;
        const float* hc = HB + cur * 1024;

        unsigned long long A0[8], A1[8];
#pragma unroll
        for (int r = 0; r < 8; r++) { A0[r] = 0ull; A1[r] = 0ull; }
#pragma unroll
        for (int j = 0; j < 8; j++) {
#pragma unroll
            for (int r = 0; r < 8; r++) {
                ulonglong2 hv = *(const ulonglong2*)(hc + r * 128 + 16 * j + 4 * ks);
                fma2(A0[r], wa[2*j], hv.x); fma2(A0[r], wa[2*j+1], hv.y);
                fma2(A1[r], wb[2*j], hv.x); fma2(A1[r], wb[2*j+1], hv.y);
            }
        }
        float s0[8], s1[8];
#pragma unroll
        for (int r = 0; r < 8; r++) {
            float u = sum2(A0[r]); u += __shfl_xor_sync(~0u, u, 1); u += __shfl_xor_sync(~0u, u, 2); s0[r] = u;
            float v = sum2(A1[r]); v += __shfl_xor_sync(~0u, v, 1); v += __shfl_xor_sync(~0u, v, 2); s1[r] = v;
        }
        float v00 = 0.f, v01 = 0.f, v10 = 0.f, v11 = 0.f;
#pragma unroll
        for (int r = 0; r < 8; r++) {
            if (r == r0) { v00 = s0[r]; v01 = s1[r]; }
            if (r == r1) { v10 = s0[r]; v11 = s1[r]; }
        }
        G[r0 * 260 + c0] = v00 + xp00;
        G[r0 * 260 + c1] = v01 + xp01;
        G[r1 * 260 + c0] = v10 + xp10;
        G[r1 * 260 + c1] = v11 + xp11;
        __syncthreads();

        {
            float gi = G[sr * 260 +       sd];
            float gf = G[sr * 260 +  64 + sd];
            float gg = G[sr * 260 + 128 + sd];
            float go = G[sr * 260 + 192 + sd];
            float iv = sigf(gi), fv = sigf(gf), ov = sigf(go);
            creg = fv * creg + iv * tanh_fast(gg);
            float hv = ov * tanh_fast(creg);
            HB[nxt * 1024 + hoff] = hv;
            unsigned pa = hb_peer + (unsigned)((nxt * 1024 + hoff) * 4);
            asm volatile("st.shared::cluster.b32 [%0], %1;" :: "r"(pa), "f"(hv) : "memory");
            outp[(size_t)t * DDIM] = hv;
        }
        CLUSTER_BAR();
    }
}

// =============================================================
// launch
// =============================================================
extern "C" void kernel_launch(void* const* d_in, const int* in_sizes, int n_in,
                              void* d_out, int out_size)
{
    const float* x     = (const float*)d_in[0];
    const float* Wih_e = (const float*)d_in[1];
    const float* Whh_e = (const float*)d_in[2];
    const float* b_e   = (const float*)d_in[3];
    const float* Wih_d = (const float*)d_in[4];
    const float* Whh_d = (const float*)d_in[5];
    const float* b_d   = (const float*)d_in[6];
    float* out = (float*)d_out;

    xp_gemm<<<2048, 512>>>(x, Wih_e, b_e);
    lstm_encoder<<<128, 512>>>(Whh_e);
    lstm_decoder<<<128, 512>>>(Wih_d, Whh_d, b_d, out);
}